// round 2
// baseline (speedup 1.0000x reference)
#include <cuda_runtime.h>
#include <cstdint>

// ---------------- fixed problem shape ----------------
#define BB   128
#define NN   8732
#define CC   21
#define NCLS 20          // classes 1..20 (background skipped)
#define TOPK 200
#define NMS_T  0.45f
#define CONF_T 0.01f

#define TB1  256         // prep kernel block
#define TB   512         // selection / global kernel block
#define EPT  18          // 512*18 = 9216 >= 8732
#define CANDCAP 1024
#define GTOT (NCLS*TOPK) // 4000
#define GPAD 4096

// ---------------- scratch (device globals; no allocations) ----------------
__device__ float  g_probsT[(size_t)BB * NCLS * NN];   // [b][c-1][i]
__device__ float4 g_boxes [(size_t)BB * NN];          // decoded clamped boxes
__device__ float  g_sc    [(size_t)BB * NCLS * TOPK]; // per-class kept scores (0 if not kept)
__device__ float4 g_bx    [(size_t)BB * NCLS * TOPK]; // per-class kept boxes

// =====================================================================
// Kernel 1: softmax (class-major output) + box decode.
// Exact-op-order arithmetic via __f*_rn intrinsics (no FMA contraction,
// immune to fast-math flags).
// =====================================================================
__global__ void __launch_bounds__(TB1)
prep_kernel(const float* __restrict__ loc,
            const float* __restrict__ conf,
            const float* __restrict__ dbox)
{
    int t = blockIdx.x * TB1 + threadIdx.x;
    if (t >= BB * NN) return;
    int b = t / NN;
    int i = t - b * NN;

    // ---- softmax over 21 classes: max-subtract, linear ascending sum ----
    const float* cf = conf + (size_t)t * CC;
    float x[CC];
#pragma unroll
    for (int c = 0; c < CC; c++) x[c] = cf[c];
    float m = x[0];
#pragma unroll
    for (int c = 1; c < CC; c++) m = fmaxf(m, x[c]);
    float e[CC];
#pragma unroll
    for (int c = 0; c < CC; c++) e[c] = expf(__fsub_rn(x[c], m));
    float s = 0.0f;
#pragma unroll
    for (int c = 0; c < CC; c++) s = __fadd_rn(s, e[c]);
#pragma unroll
    for (int c = 1; c < CC; c++)
        g_probsT[((size_t)(b * NCLS + (c - 1))) * NN + i] = __fdiv_rn(e[c], s);

    // ---- decode box (reference op order), clamp to [0,1] ----
    float4 l = ((const float4*)loc)[t];
    float4 d = ((const float4*)dbox)[i];
    float cx = __fadd_rn(d.x, __fmul_rn(__fmul_rn(l.x, 0.1f), d.z));
    float cy = __fadd_rn(d.y, __fmul_rn(__fmul_rn(l.y, 0.1f), d.w));
    float w  = __fmul_rn(d.z, expf(__fmul_rn(l.z, 0.2f)));
    float h  = __fmul_rn(d.w, expf(__fmul_rn(l.w, 0.2f)));
    float x1 = __fsub_rn(cx, __fmul_rn(w, 0.5f));
    float y1 = __fsub_rn(cy, __fmul_rn(h, 0.5f));
    float x2 = __fadd_rn(x1, w);
    float y2 = __fadd_rn(y1, h);
    x1 = fminf(fmaxf(x1, 0.0f), 1.0f);
    y1 = fminf(fmaxf(y1, 0.0f), 1.0f);
    x2 = fminf(fmaxf(x2, 0.0f), 1.0f);
    y2 = fminf(fmaxf(y2, 0.0f), 1.0f);
    g_boxes[t] = make_float4(x1, y1, x2, y2);
}

// =====================================================================
// Kernel 2: per-(batch,class) exact top-200 (score desc, idx asc) + NMS.
// One block per (b, c). blk = b*NCLS + c20.
// =====================================================================
__global__ void __launch_bounds__(TB)
per_class_kernel()
{
    __shared__ unsigned long long s_cand[CANDCAP];
    __shared__ float s_x1[TOPK], s_y1[TOPK], s_x2[TOPK], s_y2[TOPK];
    __shared__ float s_ar[TOPK], s_scv[TOPK];
    __shared__ int   s_alive[TOPK];
    __shared__ int   s_wcnt[TB / 32];
    __shared__ int   s_tot;
    __shared__ unsigned s_m;

    const int tid = threadIdx.x;
    const int blk = blockIdx.x;
    const int b   = blk / NCLS;
    const float* col = g_probsT + (size_t)blk * NN;

    // ---- scores into registers ----
    float sc[EPT];
#pragma unroll
    for (int k = 0; k < EPT; k++) {
        int i = k * TB + tid;
        sc[k] = (i < NN) ? col[i] : -1.0f;   // -1 never passes (> T >= 0.01)
    }

    // ---- block count of scores strictly above T ----
    auto bcount = [&](float T) -> int {
        int c = 0;
#pragma unroll
        for (int k = 0; k < EPT; k++) c += (sc[k] > T) ? 1 : 0;
        c = __reduce_add_sync(0xffffffffu, c);
        if ((tid & 31) == 0) s_wcnt[tid >> 5] = c;
        __syncthreads();
        if (tid == 0) {
            int t = 0;
            for (int w = 0; w < TB / 32; w++) t += s_wcnt[w];
            s_tot = t;
        }
        __syncthreads();
        int r = s_tot;
        __syncthreads();   // protect s_wcnt/s_tot for next call
        return r;
    };

    // ---- threshold: T=0.01 if few enough, else bisect float bits ----
    int M0 = bcount(CONF_T);
    float T = CONF_T;
    if (M0 > CANDCAP) {
        unsigned lo = __float_as_uint(CONF_T);   // cnt(>lo) >= TOPK (since M0 > CANDCAP)
        unsigned hi = 0x3F800000u;               // 1.0f: cnt(>hi) == 0
        while (hi - lo > 1u) {
            unsigned mid = lo + ((hi - lo) >> 1);
            int c = bcount(__uint_as_float(mid));
            if (c >= TOPK) lo = mid; else hi = mid;
        }
        T = __uint_as_float(lo);                 // 200 <= cnt(>T) <= ~200+dups
    }

    // ---- gather candidates > T into shared (unordered), then sort ----
    if (tid == 0) s_m = 0u;
    __syncthreads();
#pragma unroll
    for (int k = 0; k < EPT; k++) {
        if (sc[k] > T) {
            int i = k * TB + tid;
            unsigned slot = atomicAdd(&s_m, 1u);
            if (slot < CANDCAP)
                s_cand[slot] = ((unsigned long long)__float_as_uint(sc[k]) << 32)
                             | (unsigned long long)(0xFFFFFFFFu - (unsigned)i);
        }
    }
    __syncthreads();
    int M = min((int)s_m, CANDCAP);
    for (int i = tid; i < CANDCAP; i += TB)
        if (i >= M) s_cand[i] = 0ull;

    // bitonic sort descending, 1024 keys
    for (int size = 2; size <= CANDCAP; size <<= 1) {
        for (int stride = size >> 1; stride > 0; stride >>= 1) {
            __syncthreads();
            for (int i = tid; i < CANDCAP; i += TB) {
                int j = i ^ stride;
                if (j > i) {
                    unsigned long long a = s_cand[i], c2 = s_cand[j];
                    bool desc = ((i & size) == 0);
                    if (desc ? (a < c2) : (a > c2)) { s_cand[i] = c2; s_cand[j] = a; }
                }
            }
        }
    }
    __syncthreads();

    // ---- top-K candidates into NMS arrays ----
    int K = min(M, TOPK);
    for (int k = tid; k < TOPK; k += TB) {
        if (k < K) {
            unsigned long long key = s_cand[k];
            unsigned idx = 0xFFFFFFFFu - (unsigned)(key & 0xFFFFFFFFull);
            float4 bx = g_boxes[(size_t)b * NN + idx];
            s_x1[k] = bx.x; s_y1[k] = bx.y; s_x2[k] = bx.z; s_y2[k] = bx.w;
            s_ar[k] = (bx.z - bx.x) * (bx.w - bx.y);
            s_scv[k] = __uint_as_float((unsigned)(key >> 32));
            s_alive[k] = 1;
        } else {
            s_alive[k] = 0;
        }
    }
    __syncthreads();

    // ---- greedy NMS (serial over i; parallel over j; skip dead i cheaply) ----
    for (int i = 0; i < K; ++i) {
        if (!s_alive[i]) continue;           // uniform: no writes since last barrier
        float bx1 = s_x1[i], by1 = s_y1[i], bx2 = s_x2[i], by2 = s_y2[i];
        float bar = s_ar[i];
        for (int j = i + 1 + tid; j < K; j += TB) {
            if (s_alive[j]) {
                float xx1 = fmaxf(s_x1[j], bx1), yy1 = fmaxf(s_y1[j], by1);
                float xx2 = fminf(s_x2[j], bx2), yy2 = fminf(s_y2[j], by2);
                float inter = fmaxf(__fsub_rn(xx2, xx1), 0.0f) * fmaxf(__fsub_rn(yy2, yy1), 0.0f);
                float den = __fsub_rn(__fadd_rn(s_ar[j], bar), inter);
                float iou = __fdiv_rn(inter, den);
                if (!(iou <= NMS_T)) s_alive[j] = 0;   // NaN (0/0) suppresses, like ref
            }
        }
        __syncthreads();
    }
    __syncthreads();

    // ---- write kept scores/boxes (zeros elsewhere) ----
    for (int k = tid; k < TOPK; k += TB) {
        bool kp = (k < K) && s_alive[k];
        g_sc[(size_t)blk * TOPK + k] = kp ? s_scv[k] : 0.0f;
        g_bx[(size_t)blk * TOPK + k] =
            kp ? make_float4(s_x1[k], s_y1[k], s_x2[k], s_y2[k])
               : make_float4(0.f, 0.f, 0.f, 0.f);
    }
}

// =====================================================================
// Kernel 3: per-batch global top-200 + per-class stable compaction.
// One block per batch.
// =====================================================================
__global__ void __launch_bounds__(TB)
global_kernel(float* __restrict__ out)
{
    __shared__ unsigned long long s_key[GPAD];
    __shared__ float s_gs[TOPK];
    __shared__ int   s_gf[TOPK];
    __shared__ int   s_gp[TOPK];

    const int tid = threadIdx.x;
    const int b   = blockIdx.x;
    const float* sb = g_sc + (size_t)b * GTOT;

    for (int f = tid; f < GPAD; f += TB) {
        unsigned long long key = 0ull;
        if (f < GTOT) {
            float s = sb[f];
            if (s > 0.0f)
                key = ((unsigned long long)__float_as_uint(s) << 32)
                    | (unsigned long long)(0xFFFFFFFFu - (unsigned)f);
        }
        s_key[f] = key;
    }

    // bitonic sort descending, 4096 keys
    for (int size = 2; size <= GPAD; size <<= 1) {
        for (int stride = size >> 1; stride > 0; stride >>= 1) {
            __syncthreads();
            for (int i = tid; i < GPAD; i += TB) {
                int j = i ^ stride;
                if (j > i) {
                    unsigned long long a = s_key[i], c2 = s_key[j];
                    bool desc = ((i & size) == 0);
                    if (desc ? (a < c2) : (a > c2)) { s_key[i] = c2; s_key[j] = a; }
                }
            }
        }
    }
    __syncthreads();

    if (tid < TOPK) {
        unsigned long long key = s_key[tid];
        if (key != 0ull) {
            s_gs[tid] = __uint_as_float((unsigned)(key >> 32));
            s_gf[tid] = (int)(0xFFFFFFFFu - (unsigned)(key & 0xFFFFFFFFull));
        } else {
            s_gs[tid] = 0.0f;
            s_gf[tid] = -1;
        }
    }
    __syncthreads();

    // per-class stable position by global rank
    if (tid < TOPK && s_gf[tid] >= 0) {
        int c = s_gf[tid] / TOPK;
        int p = 0;
        for (int r = 0; r < tid; r++)
            p += (s_gf[r] >= 0 && (s_gf[r] / TOPK) == c) ? 1 : 0;
        s_gp[tid] = p;
    }
    __syncthreads();

    // zero batch slice, then scatter rows
    float* ob = out + (size_t)b * CC * TOPK * 5;
    for (int t = tid; t < CC * TOPK * 5; t += TB) ob[t] = 0.0f;
    __syncthreads();

    if (tid < TOPK && s_gf[tid] >= 0) {
        int f = s_gf[tid];
        int c = f / TOPK + 1;                 // class label 1..20
        float4 bx = g_bx[(size_t)b * GTOT + f];
        float* row = ob + ((size_t)(c * TOPK + s_gp[tid])) * 5;
        row[0] = s_gs[tid];
        row[1] = bx.x; row[2] = bx.y; row[3] = bx.z; row[4] = bx.w;
    }
}

// =====================================================================
extern "C" void kernel_launch(void* const* d_in, const int* in_sizes, int n_in,
                              void* d_out, int out_size)
{
    const float* loc  = (const float*)d_in[0];
    const float* conf = (const float*)d_in[1];
    const float* dbox = (const float*)d_in[2];
    float* out = (float*)d_out;

    prep_kernel<<<(BB * NN + TB1 - 1) / TB1, TB1>>>(loc, conf, dbox);
    per_class_kernel<<<BB * NCLS, TB>>>();
    global_kernel<<<BB, TB>>>(out);
}

// round 3
// speedup vs baseline: 1.3408x; 1.3408x over previous
#include <cuda_runtime.h>
#include <cstdint>

// ---------------- fixed problem shape ----------------
#define BB   128
#define NN   8732
#define CC   21
#define NCLS 20          // classes 1..20 (background skipped)
#define TOPK 200
#define NMS_T  0.45f
#define CONF_T 0.01f

#define TB1  256         // prep block
#define TB2  256         // per-class block
#define TB3  512         // global block
#define NWORD 7          // ceil(TOPK/32)
#define CANDCAP 1024
#define NNPAD (35*TB2)   // 8960 >= NN, uniform trip count for ballot loops
#define GTOT (NCLS*TOPK) // 4000
#define GPAD 4096

// ---------------- scratch (device globals; no allocations) ----------------
__device__ float  g_probsT[(size_t)BB * NCLS * NN];   // [b][c-1][i]
__device__ float4 g_boxes [(size_t)BB * NN];          // decoded clamped boxes
__device__ float  g_sc    [(size_t)BB * NCLS * TOPK]; // kept scores (0 if not)
__device__ float4 g_bx    [(size_t)BB * NCLS * TOPK]; // kept boxes

// =====================================================================
// Kernel 1: softmax (class-major output) + box decode. Exact op order.
// =====================================================================
__global__ void __launch_bounds__(TB1)
prep_kernel(const float* __restrict__ loc,
            const float* __restrict__ conf,
            const float* __restrict__ dbox)
{
    int t = blockIdx.x * TB1 + threadIdx.x;
    if (t >= BB * NN) return;
    int b = t / NN;
    int i = t - b * NN;

    const float* cf = conf + (size_t)t * CC;
    float x[CC];
#pragma unroll
    for (int c = 0; c < CC; c++) x[c] = cf[c];
    float m = x[0];
#pragma unroll
    for (int c = 1; c < CC; c++) m = fmaxf(m, x[c]);
    float e[CC];
#pragma unroll
    for (int c = 0; c < CC; c++) e[c] = expf(__fsub_rn(x[c], m));
    float s = 0.0f;
#pragma unroll
    for (int c = 0; c < CC; c++) s = __fadd_rn(s, e[c]);
#pragma unroll
    for (int c = 1; c < CC; c++)
        g_probsT[((size_t)(b * NCLS + (c - 1))) * NN + i] = __fdiv_rn(e[c], s);

    float4 l = ((const float4*)loc)[t];
    float4 d = ((const float4*)dbox)[i];
    float cx = __fadd_rn(d.x, __fmul_rn(__fmul_rn(l.x, 0.1f), d.z));
    float cy = __fadd_rn(d.y, __fmul_rn(__fmul_rn(l.y, 0.1f), d.w));
    float w  = __fmul_rn(d.z, expf(__fmul_rn(l.z, 0.2f)));
    float h  = __fmul_rn(d.w, expf(__fmul_rn(l.w, 0.2f)));
    float x1 = __fsub_rn(cx, __fmul_rn(w, 0.5f));
    float y1 = __fsub_rn(cy, __fmul_rn(h, 0.5f));
    float x2 = __fadd_rn(x1, w);
    float y2 = __fadd_rn(y1, h);
    x1 = fminf(fmaxf(x1, 0.0f), 1.0f);
    y1 = fminf(fmaxf(y1, 0.0f), 1.0f);
    x2 = fminf(fmaxf(x2, 0.0f), 1.0f);
    y2 = fminf(fmaxf(y2, 0.0f), 1.0f);
    g_boxes[t] = make_float4(x1, y1, x2, y2);
}

// =====================================================================
// Kernel 2: per-(batch,class) exact top-200 via radix select + bitonic,
// then NMS via parallel suppression matrix + barrier-free greedy scan.
// Dynamic shared memory, manual layout.
// =====================================================================
#define OFF_CAND   0
#define OFF_SCORE  (OFF_CAND + CANDCAP*8)              // 8192
#define OFF_X1     (OFF_SCORE + NN*4)                  // 43120
#define OFF_Y1     (OFF_X1 + TOPK*4)
#define OFF_X2     (OFF_Y1 + TOPK*4)
#define OFF_Y2     (OFF_X2 + TOPK*4)
#define OFF_AR     (OFF_Y2 + TOPK*4)
#define OFF_SCV    (OFF_AR + TOPK*4)
#define OFF_SUP    (OFF_SCV + TOPK*4)                  // 47920
#define OFF_HIST   (OFF_SUP + TOPK*NWORD*4)            // 53520
#define OFF_SUF    (OFF_HIST + 256*4)                  // 54544
#define OFF_ALIVE  (OFF_SUF + 257*4)                   // 55572
#define OFF_MISC   (OFF_ALIVE + NWORD*4 + 4)           // aligned-ish ints
#define SMEM_K2    (OFF_MISC + 32)

__global__ void __launch_bounds__(TB2)
per_class_kernel()
{
    extern __shared__ unsigned char smem[];
    unsigned long long* s_cand = (unsigned long long*)(smem + OFF_CAND);
    float*    s_scores = (float*)(smem + OFF_SCORE);
    float*    s_x1  = (float*)(smem + OFF_X1);
    float*    s_y1  = (float*)(smem + OFF_Y1);
    float*    s_x2  = (float*)(smem + OFF_X2);
    float*    s_y2  = (float*)(smem + OFF_Y2);
    float*    s_ar  = (float*)(smem + OFF_AR);
    float*    s_scv = (float*)(smem + OFF_SCV);
    unsigned* s_sup = (unsigned*)(smem + OFF_SUP);
    unsigned* s_hist = (unsigned*)(smem + OFF_HIST);
    unsigned* s_suf  = (unsigned*)(smem + OFF_SUF);     // [257]
    unsigned* s_alivew = (unsigned*)(smem + OFF_ALIVE);
    int* s_misc = (int*)(smem + OFF_MISC);              // [0]=cnt0 [1]=selbin [2]=m

    const int tid  = threadIdx.x;
    const int lane = tid & 31;
    const int blk  = blockIdx.x;          // b*NCLS + c20
    const int b    = blk / NCLS;
    const float* col = g_probsT + (size_t)blk * NN;

    if (tid < 3) s_misc[tid] = 0;
    __syncthreads();

    // ---- load scores to shared + count candidates ----
    {
        int c = 0;
        for (int i = tid; i < NN; i += TB2) {
            float s = col[i];
            s_scores[i] = s;
            c += (s > CONF_T) ? 1 : 0;
        }
        c = __reduce_add_sync(0xffffffffu, c);
        if (lane == 0) atomicAdd((unsigned*)&s_misc[0], (unsigned)c);
    }
    __syncthreads();
    const int cnt0 = s_misc[0];

    unsigned Vbits = 0;   // gather threshold bits (>= Vbits)
    bool useV = (cnt0 > 256);

    if (useV) {
        // ---- 4-pass radix select: exact 200th-largest candidate value ----
        unsigned prefix = 0;
        int R = TOPK;
        for (int p = 3; p >= 0; --p) {
            unsigned shift = 8u * (unsigned)p;
            unsigned hm = (p == 3) ? 0u : (0xFFFFFFFFu << (shift + 8u));
            for (int i = tid; i < 256; i += TB2) s_hist[i] = 0;
            __syncthreads();
            for (int base = 0; base < NNPAD; base += TB2) {
                int i = base + tid;
                bool cand = false; unsigned bin = 0;
                if (i < NN) {
                    float s = s_scores[i];
                    unsigned u = __float_as_uint(s);
                    cand = (s > CONF_T) && ((u & hm) == (prefix & hm));
                    bin = (u >> shift) & 255u;
                }
                unsigned am = __ballot_sync(0xffffffffu, cand);
                if (cand) {
                    unsigned mm = __match_any_sync(am, bin);
                    if ((unsigned)(__ffs(mm) - 1) == (unsigned)lane)
                        atomicAdd(&s_hist[bin], __popc(mm));
                }
            }
            __syncthreads();
            // suffix sums over 256 bins (warp 0)
            if (tid < 32) {
                unsigned v[8], ls[8];
                unsigned tot = 0;
#pragma unroll
                for (int j = 7; j >= 0; --j) { v[j] = s_hist[lane * 8 + j]; tot += v[j]; ls[j] = tot; }
                unsigned acc = tot;
#pragma unroll
                for (int off = 1; off < 32; off <<= 1) {
                    unsigned up = __shfl_down_sync(0xffffffffu, acc, off);
                    if (lane + off < 32) acc += up;
                }
                unsigned above = acc - tot;   // sum over lanes > this one
#pragma unroll
                for (int j = 0; j < 8; j++) s_suf[lane * 8 + j] = above + ls[j];
                if (lane == 0) s_suf[256] = 0;
            }
            __syncthreads();
            if (tid < 256) {
                if (s_suf[tid] >= (unsigned)R && s_suf[tid + 1] < (unsigned)R)
                    s_misc[1] = tid;
            }
            __syncthreads();
            int bsel = s_misc[1];
            R -= (int)s_suf[bsel + 1];
            prefix |= ((unsigned)bsel) << shift;
            __syncthreads();
        }
        Vbits = prefix;
    }

    // ---- gather candidate keys ----
    for (int i = tid; i < NN; i += TB2) {
        float s = s_scores[i];
        bool take;
        if (useV) take = (__float_as_uint(s) >= Vbits);
        else      take = (s > CONF_T);
        if (take) {
            int slot = atomicAdd(&s_misc[2], 1);
            if (slot < CANDCAP)
                s_cand[slot] = ((unsigned long long)__float_as_uint(s) << 32)
                             | (unsigned long long)(0xFFFFFFFFu - (unsigned)i);
        }
    }
    __syncthreads();
    int M = min(s_misc[2], CANDCAP);
    int SS = 256;
    while (SS < M) SS <<= 1;          // <= CANDCAP
    for (int i = tid; i < SS; i += TB2)
        if (i >= M) s_cand[i] = 0ull;

    // ---- bitonic sort descending over SS keys ----
    for (int size = 2; size <= SS; size <<= 1) {
        for (int stride = size >> 1; stride > 0; stride >>= 1) {
            __syncthreads();
            for (int i = tid; i < SS; i += TB2) {
                int j = i ^ stride;
                if (j > i) {
                    unsigned long long a = s_cand[i], c2 = s_cand[j];
                    bool desc = ((i & size) == 0);
                    if (desc ? (a < c2) : (a > c2)) { s_cand[i] = c2; s_cand[j] = a; }
                }
            }
        }
    }
    __syncthreads();

    // ---- top-K into NMS arrays ----
    const int K = min(M, TOPK);
    for (int k = tid; k < K; k += TB2) {
        unsigned long long key = s_cand[k];
        unsigned idx = 0xFFFFFFFFu - (unsigned)(key & 0xFFFFFFFFull);
        float4 bx = g_boxes[(size_t)b * NN + idx];
        s_x1[k] = bx.x; s_y1[k] = bx.y; s_x2[k] = bx.z; s_y2[k] = bx.w;
        s_ar[k] = __fmul_rn(__fsub_rn(bx.z, bx.x), __fsub_rn(bx.w, bx.y));
        s_scv[k] = __uint_as_float((unsigned)(key >> 32));
    }
    __syncthreads();

    // ---- suppression matrix: sup[i][w] bit jj -> suppress j=w*32+jj (j>i) ----
    {
        int ntask = K * NWORD;
        for (int t = tid; t < ntask; t += TB2) {
            int i = t / NWORD, w = t - i * NWORD;
            float bx1 = s_x1[i], by1 = s_y1[i], bx2 = s_x2[i], by2 = s_y2[i];
            float bar = s_ar[i];
            unsigned bits = 0;
            int j0 = w * 32;
#pragma unroll 4
            for (int jj = 0; jj < 32; jj++) {
                int j = j0 + jj;
                if (j > i && j < K) {
                    float xx1 = fmaxf(s_x1[j], bx1), yy1 = fmaxf(s_y1[j], by1);
                    float xx2 = fminf(s_x2[j], bx2), yy2 = fminf(s_y2[j], by2);
                    float inter = __fmul_rn(fmaxf(__fsub_rn(xx2, xx1), 0.0f),
                                            fmaxf(__fsub_rn(yy2, yy1), 0.0f));
                    float den = __fsub_rn(__fadd_rn(s_ar[j], bar), inter);
                    float iou = __fdiv_rn(inter, den);
                    if (!(iou <= NMS_T)) bits |= (1u << jj);   // NaN suppresses
                }
            }
            s_sup[i * NWORD + w] = bits;
        }
    }
    __syncthreads();

    // ---- barrier-free greedy scan (warp 0, alive mask in registers) ----
    if (tid < 32) {
        unsigned aw[NWORD];
#pragma unroll
        for (int w = 0; w < NWORD; w++) {
            int rem = K - w * 32;
            aw[w] = (rem >= 32) ? 0xFFFFFFFFu : ((rem <= 0) ? 0u : ((1u << rem) - 1u));
        }
        int i = 0;
#pragma unroll
        for (int wb = 0; wb < NWORD; wb++) {
            for (int ii = 0; ii < 32 && i < K; ii++, i++) {
                if ((aw[wb] >> ii) & 1u) {
                    const unsigned* row = &s_sup[i * NWORD];
#pragma unroll
                    for (int w = 0; w < NWORD; w++) aw[w] &= ~row[w];
                }
            }
        }
        if (lane == 0) {
#pragma unroll
            for (int w = 0; w < NWORD; w++) s_alivew[w] = aw[w];
        }
    }
    __syncthreads();

    // ---- write kept scores/boxes ----
    for (int k = tid; k < TOPK; k += TB2) {
        bool kp = (k < K) && ((s_alivew[k >> 5] >> (k & 31)) & 1u);
        g_sc[(size_t)blk * TOPK + k] = kp ? s_scv[k] : 0.0f;
        g_bx[(size_t)blk * TOPK + k] =
            kp ? make_float4(s_x1[k], s_y1[k], s_x2[k], s_y2[k])
               : make_float4(0.f, 0.f, 0.f, 0.f);
    }
}

// =====================================================================
// Kernel 3: per-batch global top-200 (compact nonzeros, dynamic-size sort)
// + per-class stable compaction. One block per batch.
// =====================================================================
__global__ void __launch_bounds__(TB3)
global_kernel(float* __restrict__ out)
{
    __shared__ unsigned long long s_key[GPAD];
    __shared__ float s_gs[TOPK];
    __shared__ int   s_gf[TOPK];
    __shared__ int   s_gc[TOPK];
    __shared__ int   s_gp[TOPK];
    __shared__ int   s_m;

    const int tid = threadIdx.x;
    const int b   = blockIdx.x;
    const float* sb = g_sc + (size_t)b * GTOT;

    if (tid == 0) s_m = 0;
    __syncthreads();

    for (int f = tid; f < GTOT; f += TB3) {
        float s = sb[f];
        if (s > 0.0f) {
            int slot = atomicAdd(&s_m, 1);
            s_key[slot] = ((unsigned long long)__float_as_uint(s) << 32)
                        | (unsigned long long)(0xFFFFFFFFu - (unsigned)f);
        }
    }
    __syncthreads();
    int M = s_m;
    int SS = 256;
    while (SS < M) SS <<= 1;          // <= 4096
    for (int i = tid; i < SS; i += TB3)
        if (i >= M) s_key[i] = 0ull;

    for (int size = 2; size <= SS; size <<= 1) {
        for (int stride = size >> 1; stride > 0; stride >>= 1) {
            __syncthreads();
            for (int i = tid; i < SS; i += TB3) {
                int j = i ^ stride;
                if (j > i) {
                    unsigned long long a = s_key[i], c2 = s_key[j];
                    bool desc = ((i & size) == 0);
                    if (desc ? (a < c2) : (a > c2)) { s_key[i] = c2; s_key[j] = a; }
                }
            }
        }
    }
    __syncthreads();

    if (tid < TOPK) {
        unsigned long long key = s_key[tid];   // SS >= 256 > TOPK
        if (key != 0ull) {
            s_gs[tid] = __uint_as_float((unsigned)(key >> 32));
            int f = (int)(0xFFFFFFFFu - (unsigned)(key & 0xFFFFFFFFull));
            s_gf[tid] = f;
            s_gc[tid] = f / TOPK;
        } else {
            s_gs[tid] = 0.0f; s_gf[tid] = -1; s_gc[tid] = -1;
        }
    }
    __syncthreads();

    if (tid < TOPK && s_gc[tid] >= 0) {
        int c = s_gc[tid], p = 0;
        for (int r = 0; r < tid; r++) p += (s_gc[r] == c) ? 1 : 0;
        s_gp[tid] = p;
    }
    __syncthreads();

    float* ob = out + (size_t)b * CC * TOPK * 5;
    for (int t = tid; t < CC * TOPK * 5; t += TB3) ob[t] = 0.0f;
    __syncthreads();

    if (tid < TOPK && s_gf[tid] >= 0) {
        int f = s_gf[tid];
        int c = s_gc[tid] + 1;                // class label 1..20
        float4 bx = g_bx[(size_t)b * GTOT + f];
        float* row = ob + ((size_t)(c * TOPK + s_gp[tid])) * 5;
        row[0] = s_gs[tid];
        row[1] = bx.x; row[2] = bx.y; row[3] = bx.z; row[4] = bx.w;
    }
}

// =====================================================================
extern "C" void kernel_launch(void* const* d_in, const int* in_sizes, int n_in,
                              void* d_out, int out_size)
{
    const float* loc  = (const float*)d_in[0];
    const float* conf = (const float*)d_in[1];
    const float* dbox = (const float*)d_in[2];
    float* out = (float*)d_out;

    cudaFuncSetAttribute(per_class_kernel,
                         cudaFuncAttributeMaxDynamicSharedMemorySize, SMEM_K2);

    prep_kernel<<<(BB * NN + TB1 - 1) / TB1, TB1>>>(loc, conf, dbox);
    per_class_kernel<<<BB * NCLS, TB2, SMEM_K2>>>();
    global_kernel<<<BB, TB3>>>(out);
}

// round 4
// speedup vs baseline: 1.9764x; 1.4741x over previous
#include <cuda_runtime.h>
#include <cstdint>

// ---------------- fixed problem shape ----------------
#define BB   128
#define NN   8732
#define CC   21
#define NCLS 20          // classes 1..20 (background skipped)
#define TOPK 200
#define NMS_T  0.45f
#define CONF_T 0.01f

#define TB1  256         // prep block
#define TB2  256         // per-class block
#define TB3  512         // global block
#define NWORD 7          // ceil(TOPK/32)
#define CANDCAP 1024
#define NNPAD (35*TB2)   // 8960 >= NN, uniform trip count for ballot loops
#define GTOT (NCLS*TOPK) // 4000
#define GPAD 4096

#define UBASE 0x3C000000u   // bits of 0.0078125; all scores>0.01 are above this
#define NBIN  2048          // bin = (u - UBASE) >> 15  in [71, 1792]

// ---------------- scratch (device globals; no allocations) ----------------
__device__ float  g_probsT[(size_t)BB * NCLS * NN];   // [b][c-1][i]
__device__ float4 g_boxes [(size_t)BB * NN];          // decoded clamped boxes
__device__ float  g_sc    [(size_t)BB * NCLS * TOPK]; // kept scores (0 if not)
__device__ float4 g_bx    [(size_t)BB * NCLS * TOPK]; // kept boxes

// =====================================================================
// Kernel 1: softmax (class-major output) + box decode. Exact op order.
// =====================================================================
__global__ void __launch_bounds__(TB1)
prep_kernel(const float* __restrict__ loc,
            const float* __restrict__ conf,
            const float* __restrict__ dbox)
{
    int t = blockIdx.x * TB1 + threadIdx.x;
    if (t >= BB * NN) return;
    int b = t / NN;
    int i = t - b * NN;

    const float* cf = conf + (size_t)t * CC;
    float x[CC];
#pragma unroll
    for (int c = 0; c < CC; c++) x[c] = cf[c];
    float m = x[0];
#pragma unroll
    for (int c = 1; c < CC; c++) m = fmaxf(m, x[c]);
    float e[CC];
#pragma unroll
    for (int c = 0; c < CC; c++) e[c] = expf(__fsub_rn(x[c], m));
    float s = 0.0f;
#pragma unroll
    for (int c = 0; c < CC; c++) s = __fadd_rn(s, e[c]);
#pragma unroll
    for (int c = 1; c < CC; c++)
        g_probsT[((size_t)(b * NCLS + (c - 1))) * NN + i] = __fdiv_rn(e[c], s);

    float4 l = ((const float4*)loc)[t];
    float4 d = ((const float4*)dbox)[i];
    float cx = __fadd_rn(d.x, __fmul_rn(__fmul_rn(l.x, 0.1f), d.z));
    float cy = __fadd_rn(d.y, __fmul_rn(__fmul_rn(l.y, 0.1f), d.w));
    float w  = __fmul_rn(d.z, expf(__fmul_rn(l.z, 0.2f)));
    float h  = __fmul_rn(d.w, expf(__fmul_rn(l.w, 0.2f)));
    float x1 = __fsub_rn(cx, __fmul_rn(w, 0.5f));
    float y1 = __fsub_rn(cy, __fmul_rn(h, 0.5f));
    float x2 = __fadd_rn(x1, w);
    float y2 = __fadd_rn(y1, h);
    x1 = fminf(fmaxf(x1, 0.0f), 1.0f);
    y1 = fminf(fmaxf(y1, 0.0f), 1.0f);
    x2 = fminf(fmaxf(x2, 0.0f), 1.0f);
    y2 = fminf(fmaxf(y2, 0.0f), 1.0f);
    g_boxes[t] = make_float4(x1, y1, x2, y2);
}

// =====================================================================
// Kernel 2: per-(batch,class) top-200 via 1-pass histogram threshold +
// bitonic sort, NMS via triangular suppression matrix + serial bit-scan.
// Static shared ~26.8KB -> 8 blocks/SM.
// =====================================================================
__global__ void __launch_bounds__(TB2)
per_class_kernel()
{
    __shared__ unsigned s_hist[NBIN];
    __shared__ unsigned long long s_cand[CANDCAP];
    __shared__ float s_x1[TOPK], s_y1[TOPK], s_x2[TOPK], s_y2[TOPK];
    __shared__ float s_ar[TOPK], s_scv[TOPK];
    __shared__ unsigned s_sup[TOPK * NWORD];
    __shared__ unsigned s_alivew[NWORD];
    __shared__ unsigned s_wsum[TB2 / 32];
    __shared__ int s_misc[4];        // [1]=threshold bin (-1 none) [2]=slot count

    const int tid  = threadIdx.x;
    const int lane = tid & 31;
    const int wid  = tid >> 5;
    const int blk  = blockIdx.x;          // b*NCLS + c20
    const int b    = blk / NCLS;
    const float* __restrict__ col = g_probsT + (size_t)blk * NN;

    for (int i = tid; i < NBIN; i += TB2) s_hist[i] = 0;
    if (tid < 4) s_misc[tid] = (tid == 1) ? -1 : 0;
    __syncthreads();

    // ---- pass 1: histogram of candidate score bits ----
    for (int i = tid; i < NN; i += TB2) {
        float s = col[i];
        if (s > CONF_T)
            atomicAdd(&s_hist[(__float_as_uint(s) - UBASE) >> 15], 1u);
    }
    __syncthreads();

    // ---- block suffix-scan over 2048 bins; find threshold bin B ----
    {
        unsigned locs[8];
        unsigned tot = 0;
        int b0 = tid * 8;
#pragma unroll
        for (int j = 7; j >= 0; --j) { tot += s_hist[b0 + j]; locs[j] = tot; }
        unsigned acc = tot;
#pragma unroll
        for (int off = 1; off < 32; off <<= 1) {
            unsigned up = __shfl_down_sync(0xffffffffu, acc, off);
            if (lane + off < 32) acc += up;
        }
        if (lane == 0) s_wsum[wid] = acc;        // warp total
        __syncthreads();
        unsigned above = acc - tot;              // within-warp lanes > lane
        for (int w = wid + 1; w < TB2 / 32; w++) above += s_wsum[w];
        // suffix(bin b0+j) = above + locs[j]
#pragma unroll
        for (int j = 0; j < 8; j++) {
            unsigned suf  = above + locs[j];
            unsigned nsuf = (j < 7) ? (above + locs[j + 1]) : above;
            if (suf >= (unsigned)TOPK && nsuf < (unsigned)TOPK)
                s_misc[1] = b0 + j;
        }
    }
    __syncthreads();
    const int Bbin = s_misc[1];
    const unsigned Ugate = (Bbin >= 0) ? (UBASE + ((unsigned)Bbin << 15)) : 0u;

    // ---- pass 2: gather candidates (warp-aggregated slot allocation) ----
    for (int base = 0; base < NNPAD; base += TB2) {
        int i = base + tid;
        bool take = false; float s = 0.0f;
        if (i < NN) {
            s = col[i];
            take = (s > CONF_T) && (__float_as_uint(s) >= Ugate);
        }
        unsigned am = __ballot_sync(0xffffffffu, take);
        if (am) {
            int leader = __ffs(am) - 1;
            int slot0 = 0;
            if (lane == leader) slot0 = atomicAdd(&s_misc[2], __popc(am));
            slot0 = __shfl_sync(0xffffffffu, slot0, leader);
            if (take) {
                int slot = slot0 + __popc(am & ((1u << lane) - 1u));
                if (slot < CANDCAP)
                    s_cand[slot] = ((unsigned long long)__float_as_uint(s) << 32)
                                 | (unsigned long long)(0xFFFFFFFFu - (unsigned)i);
            }
        }
    }
    __syncthreads();
    const int M = min(s_misc[2], CANDCAP);
    int SS = 256;
    while (SS < M) SS <<= 1;
    for (int i = tid; i < SS; i += TB2)
        if (i >= M) s_cand[i] = 0ull;

    // ---- bitonic sort descending over SS keys ----
    for (int size = 2; size <= SS; size <<= 1) {
        for (int stride = size >> 1; stride > 0; stride >>= 1) {
            __syncthreads();
            for (int i = tid; i < SS; i += TB2) {
                int j = i ^ stride;
                if (j > i) {
                    unsigned long long a = s_cand[i], c2 = s_cand[j];
                    bool desc = ((i & size) == 0);
                    if (desc ? (a < c2) : (a > c2)) { s_cand[i] = c2; s_cand[j] = a; }
                }
            }
        }
    }
    __syncthreads();

    // ---- top-K into NMS arrays ----
    const int K = min(M, TOPK);
    for (int k = tid; k < K; k += TB2) {
        unsigned long long key = s_cand[k];
        unsigned idx = 0xFFFFFFFFu - (unsigned)(key & 0xFFFFFFFFull);
        float4 bx = g_boxes[(size_t)b * NN + idx];
        s_x1[k] = bx.x; s_y1[k] = bx.y; s_x2[k] = bx.z; s_y2[k] = bx.w;
        s_ar[k] = __fmul_rn(__fsub_rn(bx.z, bx.x), __fsub_rn(bx.w, bx.y));
        s_scv[k] = __uint_as_float((unsigned)(key >> 32));
    }
    __syncthreads();

    // ---- triangular suppression matrix ----
    {
        int ntask = K * NWORD;
        for (int t = tid; t < ntask; t += TB2) {
            int i = t / NWORD, w = t - i * NWORD;
            int j0 = w * 32;
            int jlo = max(j0, i + 1), jhi = min(j0 + 32, K);
            unsigned bits = 0u;
            if (jlo < jhi) {
                float bx1 = s_x1[i], by1 = s_y1[i], bx2 = s_x2[i], by2 = s_y2[i];
                float bar = s_ar[i];
                for (int j = jlo; j < jhi; j++) {
                    float xx1 = fmaxf(s_x1[j], bx1), yy1 = fmaxf(s_y1[j], by1);
                    float xx2 = fminf(s_x2[j], bx2), yy2 = fminf(s_y2[j], by2);
                    float iw = fmaxf(__fsub_rn(xx2, xx1), 0.0f);
                    float ih = fmaxf(__fsub_rn(yy2, yy1), 0.0f);
                    float inter = __fmul_rn(iw, ih);
                    float den = __fsub_rn(__fadd_rn(s_ar[j], bar), inter);
                    bool sup;
                    if (inter > 0.0f) sup = !(__fdiv_rn(inter, den) <= NMS_T);
                    else              sup = (den == 0.0f);   // 0/0 -> NaN -> suppress
                    if (sup) bits |= 1u << (j - j0);
                }
            }
            s_sup[i * NWORD + w] = bits;
        }
    }
    __syncthreads();

    // ---- serial greedy bit-scan (warp 0; alive mask in registers) ----
    if (tid < 32) {
        unsigned aw[NWORD];
#pragma unroll
        for (int w = 0; w < NWORD; w++) {
            int rem = K - w * 32;
            aw[w] = (rem >= 32) ? 0xFFFFFFFFu : ((rem <= 0) ? 0u : ((1u << rem) - 1u));
        }
        int i = 0;
#pragma unroll
        for (int wb = 0; wb < NWORD; wb++) {
            for (int ii = 0; ii < 32 && i < K; ii++, i++) {
                if ((aw[wb] >> ii) & 1u) {
                    const unsigned* row = &s_sup[i * NWORD];
#pragma unroll
                    for (int w = 0; w < NWORD; w++)
                        if (w >= wb) aw[w] &= ~row[w];   // words < wb are all-zero rows
                }
            }
        }
        if (lane == 0) {
#pragma unroll
            for (int w = 0; w < NWORD; w++) s_alivew[w] = aw[w];
        }
    }
    __syncthreads();

    // ---- write kept scores/boxes ----
    for (int k = tid; k < TOPK; k += TB2) {
        bool kp = (k < K) && ((s_alivew[k >> 5] >> (k & 31)) & 1u);
        g_sc[(size_t)blk * TOPK + k] = kp ? s_scv[k] : 0.0f;
        g_bx[(size_t)blk * TOPK + k] =
            kp ? make_float4(s_x1[k], s_y1[k], s_x2[k], s_y2[k])
               : make_float4(0.f, 0.f, 0.f, 0.f);
    }
}

// =====================================================================
// Kernel 3: per-batch global top-200 (compact nonzeros, dynamic-size sort)
// + per-class stable compaction. One block per batch.
// =====================================================================
__global__ void __launch_bounds__(TB3)
global_kernel(float* __restrict__ out)
{
    __shared__ unsigned long long s_key[GPAD];
    __shared__ float s_gs[TOPK];
    __shared__ int   s_gf[TOPK];
    __shared__ int   s_gc[TOPK];
    __shared__ int   s_gp[TOPK];
    __shared__ int   s_m;

    const int tid = threadIdx.x;
    const int b   = blockIdx.x;
    const float* sb = g_sc + (size_t)b * GTOT;

    if (tid == 0) s_m = 0;
    __syncthreads();

    for (int f = tid; f < GTOT; f += TB3) {
        float s = sb[f];
        if (s > 0.0f) {
            int slot = atomicAdd(&s_m, 1);
            s_key[slot] = ((unsigned long long)__float_as_uint(s) << 32)
                        | (unsigned long long)(0xFFFFFFFFu - (unsigned)f);
        }
    }
    __syncthreads();
    int M = s_m;
    int SS = 256;
    while (SS < M) SS <<= 1;          // <= 4096
    for (int i = tid; i < SS; i += TB3)
        if (i >= M) s_key[i] = 0ull;

    for (int size = 2; size <= SS; size <<= 1) {
        for (int stride = size >> 1; stride > 0; stride >>= 1) {
            __syncthreads();
            for (int i = tid; i < SS; i += TB3) {
                int j = i ^ stride;
                if (j > i) {
                    unsigned long long a = s_key[i], c2 = s_key[j];
                    bool desc = ((i & size) == 0);
                    if (desc ? (a < c2) : (a > c2)) { s_key[i] = c2; s_key[j] = a; }
                }
            }
        }
    }
    __syncthreads();

    if (tid < TOPK) {
        unsigned long long key = s_key[tid];   // SS >= 256 > TOPK
        if (key != 0ull) {
            s_gs[tid] = __uint_as_float((unsigned)(key >> 32));
            int f = (int)(0xFFFFFFFFu - (unsigned)(key & 0xFFFFFFFFull));
            s_gf[tid] = f;
            s_gc[tid] = f / TOPK;
        } else {
            s_gs[tid] = 0.0f; s_gf[tid] = -1; s_gc[tid] = -1;
        }
    }
    __syncthreads();

    if (tid < TOPK && s_gc[tid] >= 0) {
        int c = s_gc[tid], p = 0;
        for (int r = 0; r < tid; r++) p += (s_gc[r] == c) ? 1 : 0;
        s_gp[tid] = p;
    }
    __syncthreads();

    float* ob = out + (size_t)b * CC * TOPK * 5;
    for (int t = tid; t < CC * TOPK * 5; t += TB3) ob[t] = 0.0f;
    __syncthreads();

    if (tid < TOPK && s_gf[tid] >= 0) {
        int f = s_gf[tid];
        int c = s_gc[tid] + 1;                // class label 1..20
        float4 bx = g_bx[(size_t)b * GTOT + f];
        float* row = ob + ((size_t)(c * TOPK + s_gp[tid])) * 5;
        row[0] = s_gs[tid];
        row[1] = bx.x; row[2] = bx.y; row[3] = bx.z; row[4] = bx.w;
    }
}

// =====================================================================
extern "C" void kernel_launch(void* const* d_in, const int* in_sizes, int n_in,
                              void* d_out, int out_size)
{
    const float* loc  = (const float*)d_in[0];
    const float* conf = (const float*)d_in[1];
    const float* dbox = (const float*)d_in[2];
    float* out = (float*)d_out;

    prep_kernel<<<(BB * NN + TB1 - 1) / TB1, TB1>>>(loc, conf, dbox);
    per_class_kernel<<<BB * NCLS, TB2>>>();
    global_kernel<<<BB, TB3>>>(out);
}

// round 6
// speedup vs baseline: 2.0929x; 1.0590x over previous
#include <cuda_runtime.h>
#include <cstdint>

// ---------------- fixed problem shape ----------------
#define BB   128
#define NN   8732
#define NNF4 2183        // NN/4 exactly
#define CC   21
#define NCLS 20          // classes 1..20 (background skipped)
#define TOPK 200
#define NMS_T  0.45f
#define CONF_T 0.01f

#define TB1  256         // prep block
#define TB2  256         // per-class block
#define TB3  512         // global block
#define NWORD 7          // ceil(TOPK/32)
#define CANDCAP 1024
#define GTOT (NCLS*TOPK) // 4000
#define GPAD 4096

#define UBASE 0x3C000000u   // bits of 0.0078125; all scores>0.01 are above this
#define NBIN  2048          // bin = (u - UBASE) >> 15

// 0.45f = 0x3EE66666. +/-8 ulps brackets: band ~ +/-9*2^-24 relative,
// strictly wider than (1 ulp div error) + (1 ulp bracket-mul error).
#define T_HI __uint_as_float(0x3EE6666Eu)
#define T_LO __uint_as_float(0x3EE6665Eu)

// ---------------- scratch (device globals; no allocations) ----------------
__device__ float  g_probsT[(size_t)BB * NCLS * NN];   // [b][c-1][i]
__device__ float4 g_boxes [(size_t)BB * NN];          // decoded clamped boxes
__device__ float  g_sc    [(size_t)BB * NCLS * TOPK]; // kept scores (0 if not)
__device__ float4 g_bx    [(size_t)BB * NCLS * TOPK]; // kept boxes

// =====================================================================
// Kernel 1: softmax (class-major output) + box decode. Exact op order.
// =====================================================================
__global__ void __launch_bounds__(TB1)
prep_kernel(const float* __restrict__ loc,
            const float* __restrict__ conf,
            const float* __restrict__ dbox)
{
    int t = blockIdx.x * TB1 + threadIdx.x;
    if (t >= BB * NN) return;
    int b = t / NN;
    int i = t - b * NN;

    const float* cf = conf + (size_t)t * CC;
    float x[CC];
#pragma unroll
    for (int c = 0; c < CC; c++) x[c] = cf[c];
    float m = x[0];
#pragma unroll
    for (int c = 1; c < CC; c++) m = fmaxf(m, x[c]);
    float e[CC];
#pragma unroll
    for (int c = 0; c < CC; c++) e[c] = expf(__fsub_rn(x[c], m));
    float s = 0.0f;
#pragma unroll
    for (int c = 0; c < CC; c++) s = __fadd_rn(s, e[c]);
#pragma unroll
    for (int c = 1; c < CC; c++)
        g_probsT[((size_t)(b * NCLS + (c - 1))) * NN + i] = __fdiv_rn(e[c], s);

    float4 l = ((const float4*)loc)[t];
    float4 d = ((const float4*)dbox)[i];
    float cx = __fadd_rn(d.x, __fmul_rn(__fmul_rn(l.x, 0.1f), d.z));
    float cy = __fadd_rn(d.y, __fmul_rn(__fmul_rn(l.y, 0.1f), d.w));
    float w  = __fmul_rn(d.z, expf(__fmul_rn(l.z, 0.2f)));
    float h  = __fmul_rn(d.w, expf(__fmul_rn(l.w, 0.2f)));
    float x1 = __fsub_rn(cx, __fmul_rn(w, 0.5f));
    float y1 = __fsub_rn(cy, __fmul_rn(h, 0.5f));
    float x2 = __fadd_rn(x1, w);
    float y2 = __fadd_rn(y1, h);
    x1 = fminf(fmaxf(x1, 0.0f), 1.0f);
    y1 = fminf(fmaxf(y1, 0.0f), 1.0f);
    x2 = fminf(fmaxf(x2, 0.0f), 1.0f);
    y2 = fminf(fmaxf(y2, 0.0f), 1.0f);
    g_boxes[t] = make_float4(x1, y1, x2, y2);
}

// =====================================================================
// Kernel 2: per-(batch,class) top-200 via 1-pass histogram threshold +
// bitonic sort, NMS via triangular suppression matrix (division-free
// IoU compare w/ exact fallback) + serial bit-scan.
// =====================================================================
__global__ void __launch_bounds__(TB2)
per_class_kernel()
{
    __shared__ unsigned s_hist[NBIN];
    __shared__ unsigned long long s_cand[CANDCAP];
    __shared__ float4 s_box[TOPK];
    __shared__ float s_ar[TOPK], s_scv[TOPK];
    __shared__ unsigned s_sup[TOPK * NWORD];
    __shared__ unsigned s_alivew[NWORD];
    __shared__ unsigned s_wsum[TB2 / 32];
    __shared__ int s_misc[4];        // [1]=threshold bin (-1 none) [2]=slot count

    const int tid  = threadIdx.x;
    const int lane = tid & 31;
    const int wid  = tid >> 5;
    const int blk  = blockIdx.x;          // b*NCLS + c20
    const int b    = blk / NCLS;
    const float4* __restrict__ col4 =
        (const float4*)(g_probsT + (size_t)blk * NN);

    for (int i = tid; i < NBIN; i += TB2) s_hist[i] = 0;
    if (tid < 4) s_misc[tid] = (tid == 1) ? -1 : 0;
    __syncthreads();

    // ---- pass 1: histogram of candidate score bits (float4 loads) ----
    for (int i4 = tid; i4 < NNF4; i4 += TB2) {
        float4 v = col4[i4];
        if (v.x > CONF_T) atomicAdd(&s_hist[(__float_as_uint(v.x) - UBASE) >> 15], 1u);
        if (v.y > CONF_T) atomicAdd(&s_hist[(__float_as_uint(v.y) - UBASE) >> 15], 1u);
        if (v.z > CONF_T) atomicAdd(&s_hist[(__float_as_uint(v.z) - UBASE) >> 15], 1u);
        if (v.w > CONF_T) atomicAdd(&s_hist[(__float_as_uint(v.w) - UBASE) >> 15], 1u);
    }
    __syncthreads();

    // ---- block suffix-scan over 2048 bins; find threshold bin ----
    {
        unsigned locs[8];
        unsigned tot = 0;
        int b0 = tid * 8;
#pragma unroll
        for (int j = 7; j >= 0; --j) { tot += s_hist[b0 + j]; locs[j] = tot; }
        unsigned acc = tot;
#pragma unroll
        for (int off = 1; off < 32; off <<= 1) {
            unsigned up = __shfl_down_sync(0xffffffffu, acc, off);
            if (lane + off < 32) acc += up;
        }
        if (lane == 0) s_wsum[wid] = acc;        // warp total
        __syncthreads();
        unsigned above = acc - tot;              // within-warp lanes > lane
        for (int w = wid + 1; w < TB2 / 32; w++) above += s_wsum[w];
#pragma unroll
        for (int j = 0; j < 8; j++) {
            unsigned suf  = above + locs[j];
            unsigned nsuf = (j < 7) ? (above + locs[j + 1]) : above;
            if (suf >= (unsigned)TOPK && nsuf < (unsigned)TOPK)
                s_misc[1] = b0 + j;
        }
    }
    __syncthreads();
    const int Bbin = s_misc[1];
    const unsigned Ugate = (Bbin >= 0) ? (UBASE + ((unsigned)Bbin << 15)) : 0u;

    // ---- pass 2: gather candidates (warp-aggregated slot allocation) ----
    for (int i4 = tid; i4 < NNF4 + (TB2 - NNF4 % TB2); i4 += TB2) {
        float v[4] = {0.f, 0.f, 0.f, 0.f};
        if (i4 < NNF4) {
            float4 t4 = col4[i4];
            v[0] = t4.x; v[1] = t4.y; v[2] = t4.z; v[3] = t4.w;
        }
#pragma unroll
        for (int k = 0; k < 4; k++) {
            float s = v[k];
            bool take = (s > CONF_T) && (__float_as_uint(s) >= Ugate);
            unsigned am = __ballot_sync(0xffffffffu, take);
            if (am) {
                int leader = __ffs(am) - 1;
                int slot0 = 0;
                if (lane == leader) slot0 = atomicAdd(&s_misc[2], __popc(am));
                slot0 = __shfl_sync(0xffffffffu, slot0, leader);
                if (take) {
                    int slot = slot0 + __popc(am & ((1u << lane) - 1u));
                    unsigned idx = (unsigned)(i4 * 4 + k);
                    if (slot < CANDCAP)
                        s_cand[slot] = ((unsigned long long)__float_as_uint(s) << 32)
                                     | (unsigned long long)(0xFFFFFFFFu - idx);
                }
            }
        }
    }
    __syncthreads();
    const int M = min(s_misc[2], CANDCAP);
    int SS = 256;
    while (SS < M) SS <<= 1;
    for (int i = tid; i < SS; i += TB2)
        if (i >= M) s_cand[i] = 0ull;

    // ---- bitonic sort descending over SS keys ----
    for (int size = 2; size <= SS; size <<= 1) {
        for (int stride = size >> 1; stride > 0; stride >>= 1) {
            __syncthreads();
            for (int i = tid; i < SS; i += TB2) {
                int j = i ^ stride;
                if (j > i) {
                    unsigned long long a = s_cand[i], c2 = s_cand[j];
                    bool desc = ((i & size) == 0);
                    if (desc ? (a < c2) : (a > c2)) { s_cand[i] = c2; s_cand[j] = a; }
                }
            }
        }
    }
    __syncthreads();

    // ---- top-K into NMS arrays ----
    const int K = min(M, TOPK);
    for (int k = tid; k < K; k += TB2) {
        unsigned long long key = s_cand[k];
        unsigned idx = 0xFFFFFFFFu - (unsigned)(key & 0xFFFFFFFFull);
        float4 bx = g_boxes[(size_t)b * NN + idx];
        s_box[k] = bx;
        s_ar[k] = __fmul_rn(__fsub_rn(bx.z, bx.x), __fsub_rn(bx.w, bx.y));
        s_scv[k] = __uint_as_float((unsigned)(key >> 32));
    }
    __syncthreads();

    // ---- triangular suppression matrix (division-free compare) ----
    {
        int ntask = K * NWORD;
        for (int t = tid; t < ntask; t += TB2) {
            int i = t / NWORD, w = t - i * NWORD;
            int j0 = w * 32;
            int jlo = max(j0, i + 1), jhi = min(j0 + 32, K);
            unsigned bits = 0u;
            if (jlo < jhi) {
                float4 bi = s_box[i];
                float bar = s_ar[i];
                for (int j = jlo; j < jhi; j++) {
                    float4 bj = s_box[j];
                    float xx1 = fmaxf(bj.x, bi.x), yy1 = fmaxf(bj.y, bi.y);
                    float xx2 = fminf(bj.z, bi.z), yy2 = fminf(bj.w, bi.w);
                    float iw = fmaxf(__fsub_rn(xx2, xx1), 0.0f);
                    float ih = fmaxf(__fsub_rn(yy2, yy1), 0.0f);
                    float inter = __fmul_rn(iw, ih);
                    float den = __fsub_rn(__fadd_rn(s_ar[j], bar), inter);
                    bool sup;
                    if (inter > 0.0f) {
                        // bracket fl(inter/den) vs 0.45 without dividing
                        if (inter > __fmul_rn(den, T_HI))      sup = true;
                        else if (inter < __fmul_rn(den, T_LO)) sup = false;
                        else sup = !(__fdiv_rn(inter, den) <= NMS_T); // rare exact path
                    } else {
                        sup = (den == 0.0f);   // 0/0 -> NaN -> suppress
                    }
                    if (sup) bits |= 1u << (j - j0);
                }
            }
            s_sup[i * NWORD + w] = bits;
        }
    }
    __syncthreads();

    // ---- serial greedy bit-scan (warp 0; alive mask in registers) ----
    if (tid < 32) {
        unsigned aw[NWORD];
#pragma unroll
        for (int w = 0; w < NWORD; w++) {
            int rem = K - w * 32;
            aw[w] = (rem >= 32) ? 0xFFFFFFFFu : ((rem <= 0) ? 0u : ((1u << rem) - 1u));
        }
        int i = 0;
#pragma unroll
        for (int wb = 0; wb < NWORD; wb++) {
            for (int ii = 0; ii < 32 && i < K; ii++, i++) {
                if ((aw[wb] >> ii) & 1u) {
                    const unsigned* row = &s_sup[i * NWORD];
#pragma unroll
                    for (int w = 0; w < NWORD; w++)
                        if (w >= wb) aw[w] &= ~row[w];   // words < wb: rows all-zero
                }
            }
        }
        if (lane == 0) {
#pragma unroll
            for (int w = 0; w < NWORD; w++) s_alivew[w] = aw[w];
        }
    }
    __syncthreads();

    // ---- write kept scores/boxes ----
    for (int k = tid; k < TOPK; k += TB2) {
        bool kp = (k < K) && ((s_alivew[k >> 5] >> (k & 31)) & 1u);
        g_sc[(size_t)blk * TOPK + k] = kp ? s_scv[k] : 0.0f;
        float4 bx = (k < K) ? s_box[k] : make_float4(0.f, 0.f, 0.f, 0.f);
        g_bx[(size_t)blk * TOPK + k] =
            kp ? bx : make_float4(0.f, 0.f, 0.f, 0.f);
    }
}

// =====================================================================
// Kernel 3: per-batch global top-200 (compact nonzeros, dynamic-size sort)
// + per-class stable compaction. One block per batch.
// =====================================================================
__global__ void __launch_bounds__(TB3)
global_kernel(float* __restrict__ out)
{
    __shared__ unsigned long long s_key[GPAD];
    __shared__ float s_gs[TOPK];
    __shared__ int   s_gf[TOPK];
    __shared__ int   s_gc[TOPK];
    __shared__ int   s_gp[TOPK];
    __shared__ int   s_m;

    const int tid = threadIdx.x;
    const int b   = blockIdx.x;
    const float* sb = g_sc + (size_t)b * GTOT;

    if (tid == 0) s_m = 0;
    __syncthreads();

    for (int f = tid; f < GTOT; f += TB3) {
        float s = sb[f];
        if (s > 0.0f) {
            int slot = atomicAdd(&s_m, 1);
            s_key[slot] = ((unsigned long long)__float_as_uint(s) << 32)
                        | (unsigned long long)(0xFFFFFFFFu - (unsigned)f);
        }
    }
    __syncthreads();
    int M = s_m;
    int SS = 256;
    while (SS < M) SS <<= 1;          // <= 4096
    for (int i = tid; i < SS; i += TB3)
        if (i >= M) s_key[i] = 0ull;

    for (int size = 2; size <= SS; size <<= 1) {
        for (int stride = size >> 1; stride > 0; stride >>= 1) {
            __syncthreads();
            for (int i = tid; i < SS; i += TB3) {
                int j = i ^ stride;
                if (j > i) {
                    unsigned long long a = s_key[i], c2 = s_key[j];
                    bool desc = ((i & size) == 0);
                    if (desc ? (a < c2) : (a > c2)) { s_key[i] = c2; s_key[j] = a; }
                }
            }
        }
    }
    __syncthreads();

    if (tid < TOPK) {
        unsigned long long key = s_key[tid];   // SS >= 256 > TOPK
        if (key != 0ull) {
            s_gs[tid] = __uint_as_float((unsigned)(key >> 32));
            int f = (int)(0xFFFFFFFFu - (unsigned)(key & 0xFFFFFFFFull));
            s_gf[tid] = f;
            s_gc[tid] = f / TOPK;
        } else {
            s_gs[tid] = 0.0f; s_gf[tid] = -1; s_gc[tid] = -1;
        }
    }
    __syncthreads();

    if (tid < TOPK && s_gc[tid] >= 0) {
        int c = s_gc[tid], p = 0;
        for (int r = 0; r < tid; r++) p += (s_gc[r] == c) ? 1 : 0;
        s_gp[tid] = p;
    }
    __syncthreads();

    float* ob = out + (size_t)b * CC * TOPK * 5;
    for (int t = tid; t < CC * TOPK * 5; t += TB3) ob[t] = 0.0f;
    __syncthreads();

    if (tid < TOPK && s_gf[tid] >= 0) {
        int f = s_gf[tid];
        int c = s_gc[tid] + 1;                // class label 1..20
        float4 bx = g_bx[(size_t)b * GTOT + f];
        float* row = ob + ((size_t)(c * TOPK + s_gp[tid])) * 5;
        row[0] = s_gs[tid];
        row[1] = bx.x; row[2] = bx.y; row[3] = bx.z; row[4] = bx.w;
    }
}

// =====================================================================
extern "C" void kernel_launch(void* const* d_in, const int* in_sizes, int n_in,
                              void* d_out, int out_size)
{
    const float* loc  = (const float*)d_in[0];
    const float* conf = (const float*)d_in[1];
    const float* dbox = (const float*)d_in[2];
    float* out = (float*)d_out;

    prep_kernel<<<(BB * NN + TB1 - 1) / TB1, TB1>>>(loc, conf, dbox);
    per_class_kernel<<<BB * NCLS, TB2>>>();
    global_kernel<<<BB, TB3>>>(out);
}